// round 8
// baseline (speedup 1.0000x reference)
#include <cuda_runtime.h>
#include <cuda_bf16.h>
#include <cstdint>

// Problem constants (from reference)
#define BATCH 16384
#define EMBED 1024
#define SEQ   7
#define E4    (EMBED / 4)       // 256 float4 lanes per full row
#define EQ4   64                // float4 lanes per quarter (256 channels)
#define NQ    4                 // number of channel quarters (launches)
#define ROWS_PER_CTA 16
#define ROWS_PER_IT  4          // 256 threads / 64 lanes
#define THREADS 256

typedef unsigned long long u64;

// ---- f32x2 packed helpers (Blackwell) ----
__device__ __forceinline__ u64 pack2(float lo, float hi) {
    u64 r; asm("mov.b64 %0, {%1,%2};" : "=l"(r) : "f"(lo), "f"(hi)); return r;
}
__device__ __forceinline__ void unpack2(u64 v, float& lo, float& hi) {
    asm("mov.b64 {%0,%1}, %2;" : "=f"(lo), "=f"(hi) : "l"(v));
}
__device__ __forceinline__ u64 fma2(u64 a, u64 b, u64 c) {
    u64 d; asm("fma.rn.f32x2 %0, %1, %2, %3;" : "=l"(d) : "l"(a), "l"(b), "l"(c));
    return d;
}
__device__ __forceinline__ u64 mul2(u64 a, u64 b) {
    u64 d; asm("mul.rn.f32x2 %0, %1, %2;" : "=l"(d) : "l"(a), "l"(b));
    return d;
}

// packed tanh: f32 args -> f16x2 -> ONE MUFU tanh for both -> back to f32.
// Halves the MUFU instruction stream (the binding pipe).
__device__ __forceinline__ u64 tanh2(u64 z) {
    float lo, hi;
    unpack2(z, lo, hi);
    unsigned int h2;
    asm("cvt.rn.f16x2.f32 %0, %1, %2;" : "=r"(h2) : "f"(hi), "f"(lo));
    asm("tanh.approx.f16x2 %0, %0;" : "+r"(h2));
    float flo, fhi;
    asm("{\n\t"
        ".reg .f16 l, h;\n\t"
        "mov.b32 {l, h}, %2;\n\t"
        "cvt.f32.f16 %0, l;\n\t"
        "cvt.f32.f16 %1, h;\n\t"
        "}"
        : "=f"(flo), "=f"(fhi) : "r"(h2));
    return pack2(flo, fhi);
}

// scaled float4 -> two packed f32x2
__device__ __forceinline__ ulonglong2 pack4s(float4 v, float s) {
    ulonglong2 r;
    r.x = pack2(v.x * s, v.y * s);
    r.y = pack2(v.z * s, v.w * s);
    return r;
}

// One launch processes channel quarter [e4_base, e4_base+EQ4) float4-lanes
// for the whole batch (gather footprint 32.7MB -> L2-resident).
__global__ void __launch_bounds__(THREADS, 4)
conv_cascade_q_kernel(const int* __restrict__ X,
                      const float4* __restrict__ emb,   // (VOCAB, E4)
                      const float4* __restrict__ c1,    // (2, E4)
                      const float4* __restrict__ c2,    // (2, E4)
                      const float4* __restrict__ c3,    // (3, E4)
                      const float4* __restrict__ c4,    // (3, E4)
                      float4* __restrict__ out,         // (BATCH, E4)
                      int e4_base)
{
    const int lane = threadIdx.x & (EQ4 - 1);           // 0..63
    const int rsub = threadIdx.x >> 6;                  // 0..3
    const int e4   = e4_base + lane;
    const int b0   = blockIdx.x * ROWS_PER_CTA;

    // Tanh-domain scaled weights, one set per lane, computed once.
    // Layout: [0]=w10/2 [1]=w11/2 | [2]=w20/4 [3]=w21/4 [4]=b2
    //         [5..7]=w3x/4 [8]=b3 | [9..11]=w4x/4 [12]=b4
    __shared__ ulonglong2 Wsm[13][EQ4];
    __shared__ int idx[ROWS_PER_CTA][SEQ];

    if (threadIdx.x < ROWS_PER_CTA * SEQ) {
        int r = threadIdx.x / SEQ;
        int t = threadIdx.x % SEQ;
        idx[r][t] = X[(b0 + r) * SEQ + t];
    }

    if (threadIdx.x < EQ4) {
        const int l = threadIdx.x;
        const int g = e4_base + l;
        float4 a0 = c1[0 * E4 + g], a1 = c1[1 * E4 + g];
        float4 d0 = c2[0 * E4 + g], d1 = c2[1 * E4 + g];
        float4 e0 = c3[0 * E4 + g], e1 = c3[1 * E4 + g], e2 = c3[2 * E4 + g];
        float4 f0 = c4[0 * E4 + g], f1 = c4[1 * E4 + g], f2 = c4[2 * E4 + g];

        Wsm[0][l] = pack4s(a0, 0.5f);
        Wsm[1][l] = pack4s(a1, 0.5f);
        Wsm[2][l] = pack4s(d0, 0.25f);
        Wsm[3][l] = pack4s(d1, 0.25f);
        float4 b2 = make_float4(d0.x + d1.x, d0.y + d1.y, d0.z + d1.z, d0.w + d1.w);
        Wsm[4][l] = pack4s(b2, 0.25f);
        Wsm[5][l] = pack4s(e0, 0.25f);
        Wsm[6][l] = pack4s(e1, 0.25f);
        Wsm[7][l] = pack4s(e2, 0.25f);
        float4 b3 = make_float4(e0.x + e1.x + e2.x, e0.y + e1.y + e2.y,
                                e0.z + e1.z + e2.z, e0.w + e1.w + e2.w);
        Wsm[8][l] = pack4s(b3, 0.25f);
        Wsm[9][l]  = pack4s(f0, 0.25f);
        Wsm[10][l] = pack4s(f1, 0.25f);
        Wsm[11][l] = pack4s(f2, 0.25f);
        float4 b4 = make_float4(f0.x + f1.x + f2.x, f0.y + f1.y + f2.y,
                                f0.z + f1.z + f2.z, f0.w + f1.w + f2.w);
        Wsm[12][l] = pack4s(b4, 0.25f);
    }

    __syncthreads();

    const u64 HALF2 = pack2(0.5f, 0.5f);

#pragma unroll 1
    for (int it = 0; it < ROWS_PER_CTA / ROWS_PER_IT; ++it) {
        const int r = it * ROWS_PER_IT + rsub;

        // Gather 7 embedding float4s -> packed pairs.
        u64 ha[SEQ], hb[SEQ];
#pragma unroll
        for (int t = 0; t < SEQ; ++t) {
            long row = (long)idx[r][t];
            float4 h = __ldg(&emb[row * E4 + e4]);
            ha[t] = pack2(h.x, h.y);
            hb[t] = pack2(h.z, h.w);
        }

        // Stage 1 (size-2, raw input, scale 1/2, no bias)
        ulonglong2 W0 = Wsm[0][lane], W1 = Wsm[1][lane];
        u64 pa[6], pb[6];
#pragma unroll
        for (int t = 0; t < 6; ++t) {
            pa[t] = tanh2(fma2(W0.x, ha[t], mul2(W1.x, ha[t + 1])));
            pb[t] = tanh2(fma2(W0.y, hb[t], mul2(W1.y, hb[t + 1])));
        }

        // Stage 2 (size-2, tanh-domain, scale 1/4 + bias)
        ulonglong2 V0 = Wsm[2][lane], V1 = Wsm[3][lane], B2 = Wsm[4][lane];
        u64 qa[5], qb[5];
#pragma unroll
        for (int t = 0; t < 5; ++t) {
            qa[t] = tanh2(fma2(V0.x, pa[t], fma2(V1.x, pa[t + 1], B2.x)));
            qb[t] = tanh2(fma2(V0.y, pb[t], fma2(V1.y, pb[t + 1], B2.y)));
        }

        // Stage 3 (size-3)
        ulonglong2 U0 = Wsm[5][lane], U1 = Wsm[6][lane], U2 = Wsm[7][lane],
                   B3 = Wsm[8][lane];
        u64 sa[3], sb[3];
#pragma unroll
        for (int t = 0; t < 3; ++t) {
            sa[t] = tanh2(fma2(U0.x, qa[t],
                        fma2(U1.x, qa[t + 1], fma2(U2.x, qa[t + 2], B3.x))));
            sb[t] = tanh2(fma2(U0.y, qb[t],
                        fma2(U1.y, qb[t + 1], fma2(U2.y, qb[t + 2], B3.y))));
        }

        // Stage 4 (size-3) + final affine back to sigma
        ulonglong2 T0 = Wsm[9][lane], T1 = Wsm[10][lane], T2 = Wsm[11][lane],
                   B4 = Wsm[12][lane];
        u64 ra = tanh2(fma2(T0.x, sa[0],
                       fma2(T1.x, sa[1], fma2(T2.x, sa[2], B4.x))));
        u64 rb = tanh2(fma2(T0.y, sb[0],
                       fma2(T1.y, sb[1], fma2(T2.y, sb[2], B4.y))));
        ra = fma2(ra, HALF2, HALF2);
        rb = fma2(rb, HALF2, HALF2);

        float4 res;
        unpack2(ra, res.x, res.y);
        unpack2(rb, res.z, res.w);
        __stcs(&out[(long)(b0 + r) * E4 + e4], res);
    }
}

extern "C" void kernel_launch(void* const* d_in, const int* in_sizes, int n_in,
                              void* d_out, int out_size)
{
    const int*    X    = (const int*)d_in[0];
    const float4* emb  = (const float4*)d_in[1];
    const float4* c1   = (const float4*)d_in[2];
    const float4* c2   = (const float4*)d_in[3];
    const float4* c3   = (const float4*)d_in[4];
    const float4* c4   = (const float4*)d_in[5];
    float4*       out  = (float4*)d_out;

    dim3 grid(BATCH / ROWS_PER_CTA);   // 1024 CTAs per launch
    dim3 block(THREADS);
    for (int q = 0; q < NQ; ++q) {
        conv_cascade_q_kernel<<<grid, block>>>(X, emb, c1, c2, c3, c4, out,
                                               q * EQ4);
    }
}

// round 9
// speedup vs baseline: 1.9831x; 1.9831x over previous
#include <cuda_runtime.h>
#include <cuda_bf16.h>
#include <cstdint>

// Problem constants (from reference)
#define BATCH 16384
#define EMBED 1024
#define SEQ   7
#define E4    (EMBED / 4)       // 256 float4 lanes per full row
#define EQ4   64                // float4 lanes per quarter (256 channels)
#define NQ    4                 // number of channel quarters (grid.y)
#define ROWS_PER_CTA 16
#define ROWS_PER_IT  4          // 256 threads / 64 lanes
#define THREADS 256

typedef unsigned long long u64;

// ---- f32x2 packed helpers (Blackwell) ----
__device__ __forceinline__ u64 pack2(float lo, float hi) {
    u64 r; asm("mov.b64 %0, {%1,%2};" : "=l"(r) : "f"(lo), "f"(hi)); return r;
}
__device__ __forceinline__ void unpack2(u64 v, float& lo, float& hi) {
    asm("mov.b64 {%0,%1}, %2;" : "=f"(lo), "=f"(hi) : "l"(v));
}
__device__ __forceinline__ u64 fma2(u64 a, u64 b, u64 c) {
    u64 d; asm("fma.rn.f32x2 %0, %1, %2, %3;" : "=l"(d) : "l"(a), "l"(b), "l"(c));
    return d;
}
__device__ __forceinline__ u64 mul2(u64 a, u64 b) {
    u64 d; asm("mul.rn.f32x2 %0, %1, %2;" : "=l"(d) : "l"(a), "l"(b));
    return d;
}
// packed tanh via two scalar MUFU ops (f32 — no conversion glue)
__device__ __forceinline__ u64 tanh2(u64 z) {
    float lo, hi;
    unpack2(z, lo, hi);
    asm("tanh.approx.f32 %0, %0;" : "+f"(lo));
    asm("tanh.approx.f32 %0, %0;" : "+f"(hi));
    return pack2(lo, hi);
}

// scaled float4 -> two packed f32x2
__device__ __forceinline__ ulonglong2 pack4s(float4 v, float s) {
    ulonglong2 r;
    r.x = pack2(v.x * s, v.y * s);
    r.y = pack2(v.z * s, v.w * s);
    return r;
}

// blockIdx.y selects the channel quarter; blockIdx.x walks the batch.
// CTAs schedule x-fastest, so each quarter's 32.7MB gather footprint stays
// L2-resident while its CTAs run; quarter tails backfill with the next
// quarter's heads (single ramp instead of four).
__global__ void __launch_bounds__(THREADS, 4)
conv_cascade_q_kernel(const int* __restrict__ X,
                      const float4* __restrict__ emb,   // (VOCAB, E4)
                      const float4* __restrict__ c1,    // (2, E4)
                      const float4* __restrict__ c2,    // (2, E4)
                      const float4* __restrict__ c3,    // (3, E4)
                      const float4* __restrict__ c4,    // (3, E4)
                      float4* __restrict__ out)         // (BATCH, E4)
{
    const int lane = threadIdx.x & (EQ4 - 1);           // 0..63
    const int rsub = threadIdx.x >> 6;                  // 0..3
    const int e4   = blockIdx.y * EQ4 + lane;
    const int b0   = blockIdx.x * ROWS_PER_CTA;

    // Tanh-domain scaled weights, one set per lane, computed once.
    // Layout: [0]=w10/2 [1]=w11/2 | [2]=w20/4 [3]=w21/4 [4]=b2
    //         [5..7]=w3x/4 [8]=b3 | [9..11]=w4x/4 [12]=b4
    __shared__ ulonglong2 Wsm[13][EQ4];
    __shared__ int idx[ROWS_PER_CTA][SEQ];

    if (threadIdx.x < ROWS_PER_CTA * SEQ) {
        int r = threadIdx.x / SEQ;
        int t = threadIdx.x % SEQ;
        idx[r][t] = X[(b0 + r) * SEQ + t];
    }

    if (threadIdx.x < EQ4) {
        const int l = threadIdx.x;
        const int g = blockIdx.y * EQ4 + l;
        float4 a0 = c1[0 * E4 + g], a1 = c1[1 * E4 + g];
        float4 d0 = c2[0 * E4 + g], d1 = c2[1 * E4 + g];
        float4 e0 = c3[0 * E4 + g], e1 = c3[1 * E4 + g], e2 = c3[2 * E4 + g];
        float4 f0 = c4[0 * E4 + g], f1 = c4[1 * E4 + g], f2 = c4[2 * E4 + g];

        Wsm[0][l] = pack4s(a0, 0.5f);
        Wsm[1][l] = pack4s(a1, 0.5f);
        Wsm[2][l] = pack4s(d0, 0.25f);
        Wsm[3][l] = pack4s(d1, 0.25f);
        float4 b2 = make_float4(d0.x + d1.x, d0.y + d1.y, d0.z + d1.z, d0.w + d1.w);
        Wsm[4][l] = pack4s(b2, 0.25f);
        Wsm[5][l] = pack4s(e0, 0.25f);
        Wsm[6][l] = pack4s(e1, 0.25f);
        Wsm[7][l] = pack4s(e2, 0.25f);
        float4 b3 = make_float4(e0.x + e1.x + e2.x, e0.y + e1.y + e2.y,
                                e0.z + e1.z + e2.z, e0.w + e1.w + e2.w);
        Wsm[8][l] = pack4s(b3, 0.25f);
        Wsm[9][l]  = pack4s(f0, 0.25f);
        Wsm[10][l] = pack4s(f1, 0.25f);
        Wsm[11][l] = pack4s(f2, 0.25f);
        float4 b4 = make_float4(f0.x + f1.x + f2.x, f0.y + f1.y + f2.y,
                                f0.z + f1.z + f2.z, f0.w + f1.w + f2.w);
        Wsm[12][l] = pack4s(b4, 0.25f);
    }

    __syncthreads();

    const u64 HALF2 = pack2(0.5f, 0.5f);

#pragma unroll 1
    for (int it = 0; it < ROWS_PER_CTA / ROWS_PER_IT; ++it) {
        const int r = it * ROWS_PER_IT + rsub;

        // Gather 7 embedding float4s -> packed pairs.
        u64 ha[SEQ], hb[SEQ];
#pragma unroll
        for (int t = 0; t < SEQ; ++t) {
            long row = (long)idx[r][t];
            float4 h = __ldg(&emb[row * E4 + e4]);
            ha[t] = pack2(h.x, h.y);
            hb[t] = pack2(h.z, h.w);
        }

        // Stage 1 (size-2, raw input, scale 1/2, no bias)
        ulonglong2 W0 = Wsm[0][lane], W1 = Wsm[1][lane];
        u64 pa[6], pb[6];
#pragma unroll
        for (int t = 0; t < 6; ++t) {
            pa[t] = tanh2(fma2(W0.x, ha[t], mul2(W1.x, ha[t + 1])));
            pb[t] = tanh2(fma2(W0.y, hb[t], mul2(W1.y, hb[t + 1])));
        }

        // Stage 2 (size-2, tanh-domain, scale 1/4 + bias)
        ulonglong2 V0 = Wsm[2][lane], V1 = Wsm[3][lane], B2 = Wsm[4][lane];
        u64 qa[5], qb[5];
#pragma unroll
        for (int t = 0; t < 5; ++t) {
            qa[t] = tanh2(fma2(V0.x, pa[t], fma2(V1.x, pa[t + 1], B2.x)));
            qb[t] = tanh2(fma2(V0.y, pb[t], fma2(V1.y, pb[t + 1], B2.y)));
        }

        // Stage 3 (size-3)
        ulonglong2 U0 = Wsm[5][lane], U1 = Wsm[6][lane], U2 = Wsm[7][lane],
                   B3 = Wsm[8][lane];
        u64 sa[3], sb[3];
#pragma unroll
        for (int t = 0; t < 3; ++t) {
            sa[t] = tanh2(fma2(U0.x, qa[t],
                        fma2(U1.x, qa[t + 1], fma2(U2.x, qa[t + 2], B3.x))));
            sb[t] = tanh2(fma2(U0.y, qb[t],
                        fma2(U1.y, qb[t + 1], fma2(U2.y, qb[t + 2], B3.y))));
        }

        // Stage 4 (size-3) + final affine back to sigma
        ulonglong2 T0 = Wsm[9][lane], T1 = Wsm[10][lane], T2 = Wsm[11][lane],
                   B4 = Wsm[12][lane];
        u64 ra = tanh2(fma2(T0.x, sa[0],
                       fma2(T1.x, sa[1], fma2(T2.x, sa[2], B4.x))));
        u64 rb = tanh2(fma2(T0.y, sb[0],
                       fma2(T1.y, sb[1], fma2(T2.y, sb[2], B4.y))));
        ra = fma2(ra, HALF2, HALF2);
        rb = fma2(rb, HALF2, HALF2);

        float4 res;
        unpack2(ra, res.x, res.y);
        unpack2(rb, res.z, res.w);
        __stcs(&out[(long)(b0 + r) * E4 + e4], res);
    }
}

extern "C" void kernel_launch(void* const* d_in, const int* in_sizes, int n_in,
                              void* d_out, int out_size)
{
    const int*    X    = (const int*)d_in[0];
    const float4* emb  = (const float4*)d_in[1];
    const float4* c1   = (const float4*)d_in[2];
    const float4* c2   = (const float4*)d_in[3];
    const float4* c3   = (const float4*)d_in[4];
    const float4* c4   = (const float4*)d_in[5];
    float4*       out  = (float4*)d_out;

    dim3 grid(BATCH / ROWS_PER_CTA, NQ);   // (1024, 4) — x fastest => quarter order
    dim3 block(THREADS);
    conv_cascade_q_kernel<<<grid, block>>>(X, emb, c1, c2, c3, c4, out);
}

// round 11
// speedup vs baseline: 2.0010x; 1.0090x over previous
#include <cuda_runtime.h>
#include <cuda_fp16.h>
#include <cstdint>

// Problem constants (from reference)
#define BATCH 16384
#define EMBED 1024
#define SEQ   7
#define E4    (EMBED / 4)       // 256 float4 lanes per full row
#define EQ4   64                // float4 lanes per quarter (256 channels)
#define NQ    4                 // channel quarters (grid.y)
#define ROWS_PER_CTA 16
#define ROWS_PER_IT  4          // 256 threads / 64 lanes
#define THREADS 256

// reinterpret helpers
__device__ __forceinline__ __half2 u2h2(unsigned r) {
    __half2 h; *reinterpret_cast<unsigned*>(&h) = r; return h;
}
__device__ __forceinline__ unsigned h22u(__half2 h) {
    return *reinterpret_cast<unsigned*>(&h);
}
// packed f16x2 tanh: one MUFU op for two channels
__device__ __forceinline__ __half2 tanh2h(__half2 x) {
    unsigned r = h22u(x);
    asm("tanh.approx.f16x2 %0, %0;" : "+r"(r));
    return u2h2(r);
}

// scaled float pair -> half2
__device__ __forceinline__ __half2 mk2(float a, float b, float s) {
    return __floats2half2_rn(a * s, b * s);
}

// blockIdx.y = channel quarter; blockIdx.x walks the batch (x-fastest order
// keeps each quarter's 32.7MB gather footprint L2-resident).
__global__ void __launch_bounds__(THREADS, 4)
conv_cascade_q_kernel(const int* __restrict__ X,
                      const float4* __restrict__ emb,   // (VOCAB, E4)
                      const float4* __restrict__ c1,    // (2, E4)
                      const float4* __restrict__ c2,    // (2, E4)
                      const float4* __restrict__ c3,    // (3, E4)
                      const float4* __restrict__ c4,    // (3, E4)
                      float4* __restrict__ out)         // (BATCH, E4)
{
    const int lane = threadIdx.x & (EQ4 - 1);           // 0..63
    const int rsub = threadIdx.x >> 6;                  // 0..3
    const int e4   = blockIdx.y * EQ4 + lane;
    const int b0   = blockIdx.x * ROWS_PER_CTA;

    __shared__ int idx[ROWS_PER_CTA][SEQ];
    if (threadIdx.x < ROWS_PER_CTA * SEQ) {
        int r = threadIdx.x / SEQ;
        int t = threadIdx.x % SEQ;
        idx[r][t] = X[(b0 + r) * SEQ + t];
    }

    // Tanh-domain scaled weights, ALL in registers (f16x2; a = ch0/1, b = ch2/3).
    // Stage1: w/2 no bias; stages 2-4: w/4 with bias = sum(w)/4.
    float4 a0 = c1[0 * E4 + e4], a1 = c1[1 * E4 + e4];
    float4 d0 = c2[0 * E4 + e4], d1 = c2[1 * E4 + e4];
    float4 e0 = c3[0 * E4 + e4], e1 = c3[1 * E4 + e4], e2 = c3[2 * E4 + e4];
    float4 f0 = c4[0 * E4 + e4], f1 = c4[1 * E4 + e4], f2 = c4[2 * E4 + e4];

    const __half2 W10a = mk2(a0.x, a0.y, 0.5f),  W10b = mk2(a0.z, a0.w, 0.5f);
    const __half2 W11a = mk2(a1.x, a1.y, 0.5f),  W11b = mk2(a1.z, a1.w, 0.5f);
    const __half2 V0a  = mk2(d0.x, d0.y, 0.25f), V0b  = mk2(d0.z, d0.w, 0.25f);
    const __half2 V1a  = mk2(d1.x, d1.y, 0.25f), V1b  = mk2(d1.z, d1.w, 0.25f);
    const __half2 B2a  = mk2(d0.x + d1.x, d0.y + d1.y, 0.25f);
    const __half2 B2b  = mk2(d0.z + d1.z, d0.w + d1.w, 0.25f);
    const __half2 U0a  = mk2(e0.x, e0.y, 0.25f), U0b  = mk2(e0.z, e0.w, 0.25f);
    const __half2 U1a  = mk2(e1.x, e1.y, 0.25f), U1b  = mk2(e1.z, e1.w, 0.25f);
    const __half2 U2a  = mk2(e2.x, e2.y, 0.25f), U2b  = mk2(e2.z, e2.w, 0.25f);
    const __half2 B3a  = mk2(e0.x + e1.x + e2.x, e0.y + e1.y + e2.y, 0.25f);
    const __half2 B3b  = mk2(e0.z + e1.z + e2.z, e0.w + e1.w + e2.w, 0.25f);
    const __half2 T0a  = mk2(f0.x, f0.y, 0.25f), T0b  = mk2(f0.z, f0.w, 0.25f);
    const __half2 T1a  = mk2(f1.x, f1.y, 0.25f), T1b  = mk2(f1.z, f1.w, 0.25f);
    const __half2 T2a  = mk2(f2.x, f2.y, 0.25f), T2b  = mk2(f2.z, f2.w, 0.25f);
    const __half2 B4a  = mk2(f0.x + f1.x + f2.x, f0.y + f1.y + f2.y, 0.25f);
    const __half2 B4b  = mk2(f0.z + f1.z + f2.z, f0.w + f1.w + f2.w, 0.25f);
    const __half2 HALF = __float2half2_rn(0.5f);

    __syncthreads();

#pragma unroll 1
    for (int it = 0; it < ROWS_PER_CTA / ROWS_PER_IT; ++it) {
        const int r = it * ROWS_PER_IT + rsub;

        // Gather 7 embedding float4s -> f16x2 pairs (edge conversion only).
        __half2 ha[SEQ], hb[SEQ];
#pragma unroll
        for (int t = 0; t < SEQ; ++t) {
            long row = (long)idx[r][t];
            float4 h = __ldg(&emb[row * E4 + e4]);
            ha[t] = __floats2half2_rn(h.x, h.y);
            hb[t] = __floats2half2_rn(h.z, h.w);
        }

        // Stage 1 (size-2, raw input, scale 1/2, no bias)
        __half2 pa[6], pb[6];
#pragma unroll
        for (int t = 0; t < 6; ++t) {
            pa[t] = tanh2h(__hfma2(W10a, ha[t], __hmul2(W11a, ha[t + 1])));
            pb[t] = tanh2h(__hfma2(W10b, hb[t], __hmul2(W11b, hb[t + 1])));
        }

        // Stage 2 (size-2, tanh-domain, scale 1/4 + bias)
        __half2 qa[5], qb[5];
#pragma unroll
        for (int t = 0; t < 5; ++t) {
            qa[t] = tanh2h(__hfma2(V0a, pa[t], __hfma2(V1a, pa[t + 1], B2a)));
            qb[t] = tanh2h(__hfma2(V0b, pb[t], __hfma2(V1b, pb[t + 1], B2b)));
        }

        // Stage 3 (size-3)
        __half2 sa[3], sb[3];
#pragma unroll
        for (int t = 0; t < 3; ++t) {
            sa[t] = tanh2h(__hfma2(U0a, qa[t],
                        __hfma2(U1a, qa[t + 1], __hfma2(U2a, qa[t + 2], B3a))));
            sb[t] = tanh2h(__hfma2(U0b, qb[t],
                        __hfma2(U1b, qb[t + 1], __hfma2(U2b, qb[t + 2], B3b))));
        }

        // Stage 4 (size-3) + final affine back to sigma
        __half2 ra = tanh2h(__hfma2(T0a, sa[0],
                       __hfma2(T1a, sa[1], __hfma2(T2a, sa[2], B4a))));
        __half2 rb = tanh2h(__hfma2(T0b, sb[0],
                       __hfma2(T1b, sb[1], __hfma2(T2b, sb[2], B4b))));
        ra = __hfma2(ra, HALF, HALF);
        rb = __hfma2(rb, HALF, HALF);

        float2 fa = __half22float2(ra);
        float2 fb = __half22float2(rb);
        float4 res = make_float4(fa.x, fa.y, fb.x, fb.y);
        __stcs(&out[(long)(b0 + r) * E4 + e4], res);
    }
}

extern "C" void kernel_launch(void* const* d_in, const int* in_sizes, int n_in,
                              void* d_out, int out_size)
{
    const int*    X    = (const int*)d_in[0];
    const float4* emb  = (const float4*)d_in[1];
    const float4* c1   = (const float4*)d_in[2];
    const float4* c2   = (const float4*)d_in[3];
    const float4* c3   = (const float4*)d_in[4];
    const float4* c4   = (const float4*)d_in[5];
    float4*       out  = (float4*)d_out;

    dim3 grid(BATCH / ROWS_PER_CTA, NQ);   // (1024, 4) — x fastest => quarter order
    dim3 block(THREADS);
    conv_cascade_q_kernel<<<grid, block>>>(X, emb, c1, c2, c3, c4, out);
}